// round 1
// baseline (speedup 1.0000x reference)
#include <cuda_runtime.h>
#include <cuda_bf16.h>
#include <math.h>

// Problem shape (fixed by reference): B=128, T=2048, H=128
#define B_DIM 128
#define T_DIM 2048
#define H_DIM 128
#define BT (B_DIM * T_DIM)

// ---------------------------------------------------------------------------
// f32x2 packed helpers (sm_100+ packed fp32 FMA; ptxas never auto-fuses these)
// ---------------------------------------------------------------------------
__device__ __forceinline__ unsigned long long pack2(float lo, float hi) {
    unsigned long long r;
    asm("mov.b64 %0, {%1, %2};" : "=l"(r) : "f"(lo), "f"(hi));
    return r;
}
__device__ __forceinline__ unsigned long long dup2(float w) {
    unsigned long long r;
    asm("mov.b64 %0, {%1, %1};" : "=l"(r) : "f"(w));
    return r;
}
__device__ __forceinline__ void fma2(unsigned long long& d, unsigned long long a,
                                     unsigned long long b) {
    asm("fma.rn.f32x2 %0, %1, %2, %0;" : "+l"(d) : "l"(a), "l"(b));
}
__device__ __forceinline__ void unpack2(unsigned long long v, float& lo, float& hi) {
    asm("mov.b64 {%0, %1}, %2;" : "=f"(lo), "=f"(hi) : "l"(v));
}

// ---------------------------------------------------------------------------
// Kernel 1: energy[row] = sum_o W_a[o] * tanh( sum_k X[row,k] * Wc[o,k] )
// where X = [H_pos | H_dyn] (K=256) and Wc = [W_h | W_d].
// Tile: 128 rows x 128 outputs per block, K-tiles of 16. 256 threads,
// each computing an 8x8 register tile as 4x8 f32x2 accumulators (rows paired).
// ---------------------------------------------------------------------------
__global__ __launch_bounds__(256) void energy_kernel(
    const float* __restrict__ Hp, const float* __restrict__ Hd,
    const float* __restrict__ Wh, const float* __restrict__ Wd,
    const float* __restrict__ Wa, float* __restrict__ energy)
{
    __shared__ float Xs[16][132];   // [k][row], padded: stride 132 (16B-aligned rows)
    __shared__ float Ws[16][132];   // [k][out]
    __shared__ float esum[128];

    const int tid = threadIdx.x;
    const int tx = tid & 15;        // output-col group (tx*8 .. tx*8+7)
    const int ty = tid >> 4;        // row group        (ty*8 .. ty*8+7)
    const int row0 = blockIdx.x * 128;

    // W_a slice for this thread's 8 output columns
    float wa[8];
    {
        float4 w0 = *(const float4*)(Wa + tx * 8);
        float4 w1 = *(const float4*)(Wa + tx * 8 + 4);
        wa[0] = w0.x; wa[1] = w0.y; wa[2] = w0.z; wa[3] = w0.w;
        wa[4] = w1.x; wa[5] = w1.y; wa[6] = w1.z; wa[7] = w1.w;
    }

    unsigned long long acc[4][8];
    #pragma unroll
    for (int ri = 0; ri < 4; ++ri)
        #pragma unroll
        for (int j = 0; j < 8; ++j) acc[ri][j] = 0ull;  // (0.f, 0.f)

    #pragma unroll 1
    for (int kt = 0; kt < 16; ++kt) {
        const float* xsrc = (kt < 8) ? Hp : Hd;
        const float* wsrc = (kt < 8) ? Wh : Wd;
        const int kb = (kt & 7) * 16;

        __syncthreads();
        // Load 128x16 X tile (transposed into smem) -- 512 float4 loads
        #pragma unroll
        for (int i = tid; i < 512; i += 256) {
            const int r = i >> 2;
            const int q = (i & 3) << 2;
            float4 v = *(const float4*)(xsrc + ((size_t)(row0 + r) << 7) + kb + q);
            Xs[q + 0][r] = v.x; Xs[q + 1][r] = v.y;
            Xs[q + 2][r] = v.z; Xs[q + 3][r] = v.w;
        }
        // Load 128x16 W tile (transposed)
        #pragma unroll
        for (int i = tid; i < 512; i += 256) {
            const int o = i >> 2;
            const int q = (i & 3) << 2;
            float4 v = *(const float4*)(wsrc + (o << 7) + kb + q);
            Ws[q + 0][o] = v.x; Ws[q + 1][o] = v.y;
            Ws[q + 2][o] = v.z; Ws[q + 3][o] = v.w;
        }
        __syncthreads();

        #pragma unroll
        for (int kk = 0; kk < 16; ++kk) {
            const float4 xa = *(const float4*)&Xs[kk][ty * 8];
            const float4 xb = *(const float4*)&Xs[kk][ty * 8 + 4];
            const float4 wva = *(const float4*)&Ws[kk][tx * 8];
            const float4 wvb = *(const float4*)&Ws[kk][tx * 8 + 4];
            unsigned long long a2[4];
            a2[0] = pack2(xa.x, xa.y); a2[1] = pack2(xa.z, xa.w);
            a2[2] = pack2(xb.x, xb.y); a2[3] = pack2(xb.z, xb.w);
            const float wv[8] = {wva.x, wva.y, wva.z, wva.w,
                                 wvb.x, wvb.y, wvb.z, wvb.w};
            #pragma unroll
            for (int j = 0; j < 8; ++j) {
                const unsigned long long b2 = dup2(wv[j]);
                #pragma unroll
                for (int ri = 0; ri < 4; ++ri) fma2(acc[ri][j], a2[ri], b2);
            }
        }
    }

    // Epilogue: energy partials = sum_j wa[j] * tanh(z), reduce per row in smem
    __syncthreads();
    if (tid < 128) esum[tid] = 0.f;
    __syncthreads();
    #pragma unroll
    for (int ri = 0; ri < 4; ++ri) {
        float p_lo = 0.f, p_hi = 0.f;
        #pragma unroll
        for (int j = 0; j < 8; ++j) {
            float lo, hi;
            unpack2(acc[ri][j], lo, hi);
            p_lo += wa[j] * tanhf(lo);
            p_hi += wa[j] * tanhf(hi);
        }
        atomicAdd(&esum[ty * 8 + ri * 2 + 0], p_lo);
        atomicAdd(&esum[ty * 8 + ri * 2 + 1], p_hi);
    }
    __syncthreads();
    if (tid < 128) energy[row0 + tid] = esum[tid];
}

// ---------------------------------------------------------------------------
// Kernel 2: per-batch scaled softmax over T=2048.
// alpha buffer holds energy on entry, alpha on exit (in-place per block).
// ---------------------------------------------------------------------------
__global__ __launch_bounds__(256) void softmax_kernel(
    const float* __restrict__ acc_w, const float* __restrict__ ba_p,
    const float* __restrict__ beta_p, float* __restrict__ alpha)
{
    const int b = blockIdx.x;
    const int tid = threadIdx.x;
    __shared__ float sbuf[T_DIM];
    __shared__ float red[256];

    const float* aw = acc_w + (size_t)b * T_DIM;
    float* al = alpha + (size_t)b * T_DIM;

    // max of acc_w over this batch row
    float wmax = -3.4e38f;
    for (int t = tid; t < T_DIM; t += 256) wmax = fmaxf(wmax, aw[t]);
    red[tid] = wmax;
    __syncthreads();
    for (int s = 128; s > 0; s >>= 1) {
        if (tid < s) red[tid] = fmaxf(red[tid], red[tid + s]);
        __syncthreads();
    }
    const float denom = fmaxf(red[0], 1e-6f);
    __syncthreads();

    const float beta = *beta_p;
    // numerically stable softplus
    const float bpos = fmaxf(beta, 0.f) + log1pf(expf(-fabsf(beta)));
    const float ba = *ba_p;

    // scaled logits + running max
    float smax = -3.4e38f;
    for (int t = tid; t < T_DIM; t += 256) {
        const float s = (al[t] + ba) * (1.f + bpos * (aw[t] / denom));
        sbuf[t] = s;
        smax = fmaxf(smax, s);
    }
    red[tid] = smax;
    __syncthreads();
    for (int s = 128; s > 0; s >>= 1) {
        if (tid < s) red[tid] = fmaxf(red[tid], red[tid + s]);
        __syncthreads();
    }
    smax = red[0];
    __syncthreads();

    float ssum = 0.f;
    for (int t = tid; t < T_DIM; t += 256) {
        const float p = expf(sbuf[t] - smax);
        sbuf[t] = p;
        ssum += p;
    }
    red[tid] = ssum;
    __syncthreads();
    for (int s = 128; s > 0; s >>= 1) {
        if (tid < s) red[tid] += red[tid + s];
        __syncthreads();
    }
    const float inv = 1.f / red[0];
    for (int t = tid; t < T_DIM; t += 256) al[t] = sbuf[t] * inv;
}

// ---------------------------------------------------------------------------
// Kernel 3: context[b,h] = sum_t alpha[b,t] * H_pos[b,t,h]
// One block per batch; 512 threads = 128 h-lanes x 4 T-partitions.
// ---------------------------------------------------------------------------
__global__ __launch_bounds__(512) void context_kernel(
    const float* __restrict__ Hp, const float* __restrict__ alpha,
    float* __restrict__ ctx)
{
    const int b = blockIdx.x;
    const int tid = threadIdx.x;
    const int h = tid & 127;
    const int part = tid >> 7;  // 0..3

    const float* al = alpha + (size_t)b * T_DIM;
    const float* hp = Hp + ((size_t)b * T_DIM) * H_DIM + h;

    float acc = 0.f;
    const int t0 = part * (T_DIM / 4);
    #pragma unroll 8
    for (int t = 0; t < T_DIM / 4; ++t)
        acc += al[t0 + t] * hp[(size_t)(t0 + t) * H_DIM];

    __shared__ float cbuf[512];
    cbuf[tid] = acc;
    __syncthreads();
    if (part == 0)
        ctx[b * H_DIM + h] = cbuf[h] + cbuf[h + 128] + cbuf[h + 256] + cbuf[h + 384];
}

// ---------------------------------------------------------------------------
// Launch. Inputs per metadata order:
//   0 H_pos [B,T,H] f32, 1 H_dyn [B,T,H] f32, 2 acc_w [B,T] f32,
//   3 W_h [H,H] f32, 4 W_d [H,H] f32, 5 W_a [H] f32, 6 b_a [] f32, 7 beta [] f32
// Output: context [B,H] followed by alpha [B,T] (both f32).
// Energy is staged in the alpha region of d_out (softmax then rewrites it).
// ---------------------------------------------------------------------------
extern "C" void kernel_launch(void* const* d_in, const int* in_sizes, int n_in,
                              void* d_out, int out_size)
{
    const float* Hp   = (const float*)d_in[0];
    const float* Hd   = (const float*)d_in[1];
    const float* accw = (const float*)d_in[2];
    const float* Wh   = (const float*)d_in[3];
    const float* Wd   = (const float*)d_in[4];
    const float* Wa   = (const float*)d_in[5];
    const float* ba   = (const float*)d_in[6];
    const float* beta = (const float*)d_in[7];

    float* out   = (float*)d_out;
    float* ctx   = out;                    // [B, H]
    float* alpha = out + B_DIM * H_DIM;    // [B, T] (energy staging, then alpha)

    energy_kernel<<<BT / 128, 256>>>(Hp, Hd, Wh, Wd, Wa, alpha);
    softmax_kernel<<<B_DIM, 256>>>(accw, ba, beta, alpha);
    context_kernel<<<B_DIM, 512>>>(Hp, alpha, ctx);
}

// round 3
// speedup vs baseline: 2.4352x; 2.4352x over previous
#include <cuda_runtime.h>
#include <cuda_bf16.h>
#include <cstdint>
#include <math.h>

// Problem shape (fixed by reference): B=128, T=2048, H=128
#define B_DIM 128
#define T_DIM 2048
#define H_DIM 128
#define BT (B_DIM * T_DIM)

#define SW128(off) ((off) ^ (((off) >> 3) & 0x70))

__device__ __forceinline__ uint32_t smem_to_u32(const void* p) {
    uint32_t a;
    asm("{ .reg .u64 t; cvta.to.shared.u64 t, %1; cvt.u32.u64 %0, t; }"
        : "=r"(a) : "l"(p));
    return a;
}

// ldmatrix x4 (non-trans): 4 8x8 b16 matrices, per-lane row addresses
__device__ __forceinline__ void ldsm4(uint32_t* r, uint32_t addr) {
    asm volatile("ldmatrix.sync.aligned.m8n8.x4.shared.b16 {%0,%1,%2,%3}, [%4];"
                 : "=r"(r[0]), "=r"(r[1]), "=r"(r[2]), "=r"(r[3]) : "r"(addr));
}

// mma m16n8k16 row.col f32.bf16.bf16.f32
__device__ __forceinline__ void mma_bf16(float* c, const uint32_t* a,
                                         uint32_t b0, uint32_t b1) {
    asm volatile(
        "mma.sync.aligned.m16n8k16.row.col.f32.bf16.bf16.f32 "
        "{%0,%1,%2,%3}, {%4,%5,%6,%7}, {%8,%9}, {%0,%1,%2,%3};"
        : "+f"(c[0]), "+f"(c[1]), "+f"(c[2]), "+f"(c[3])
        : "r"(a[0]), "r"(a[1]), "r"(a[2]), "r"(a[3]), "r"(b0), "r"(b1));
}

// hi = truncate-to-bf16 (exact float), lo = bf16_rn(x - hi). Pack 2 hi via PRMT.
__device__ __forceinline__ uint32_t pack_hi2(float x, float y) {
    return __byte_perm(__float_as_uint(x), __float_as_uint(y), 0x7632);
}
__device__ __forceinline__ float hi_of(float x) {
    return __uint_as_float(__float_as_uint(x) & 0xFFFF0000u);
}
__device__ __forceinline__ uint32_t pack_lo2(float x, float y) {
    float lx = x - hi_of(x);
    float ly = y - hi_of(y);
    uint32_t r;
    asm("cvt.rn.bf16x2.f32 %0, %1, %2;" : "=r"(r) : "f"(ly), "f"(lx));
    return r;
}

__device__ __forceinline__ float tanh_fast(float z) {
    const float ex = __expf(2.f * z);
    return 1.f - __fdividef(2.f, ex + 1.f);
}

// ---------------------------------------------------------------------------
// Pre-converted weights: 4 K-chunks (Wh k0-63, Wh k64-127, Wd k0-63, Wd k64-127).
// Each chunk: SW128-swizzled [o][k] bf16 images, hi tile 16KB then lo tile 16KB.
// ---------------------------------------------------------------------------
__device__ __align__(16) unsigned char g_Wimg[4 * 32768];

__global__ __launch_bounds__(256) void wconv_kernel(
    const float* __restrict__ Wh, const float* __restrict__ Wd)
{
    const int idx = blockIdx.x * 256 + threadIdx.x;   // 32768 total
    const int ch  = idx >> 13;                        // 0..3
    const int rem = idx & 8191;
    const int o   = rem >> 6;                         // 0..127 (output row)
    const int kc  = rem & 63;                         // 0..63  (k within chunk)
    const float* src = (ch < 2) ? Wh : Wd;
    const float x = src[o * 128 + (ch & 1) * 64 + kc];
    const float h = hi_of(x);
    const __nv_bfloat16 l = __float2bfloat16(x - h);
    const uint32_t off = (uint32_t)(o * 128 + kc * 2);
    const uint32_t sw  = SW128(off);
    *(uint16_t*)(g_Wimg + ch * 32768 + sw) = (uint16_t)(__float_as_uint(x) >> 16);
    *(__nv_bfloat16*)(g_Wimg + ch * 32768 + 16384 + sw) = l;
}

// ---------------------------------------------------------------------------
// Energy kernel (HMMA): CTA = 128 threads (4 warps), M-tile 128 rows x N=128.
// Warp (wy,wx) covers rows wy*64..+64, cols wx*64..+64: 4 m16-tiles x 8 n8-tiles,
// 128 fp32 accumulators/thread. K=256 in 4 chunks of 64.
// Split-bf16: D = Ahi*Bhi + Ahi*Blo + Alo*Bhi.
// Epilogue: energy[row] = sum_n Wa[n] * tanh(D[row,n]).
// ---------------------------------------------------------------------------
#define A_HI 1024
#define A_LO (1024 + 16384)
#define B_HI (1024 + 32768)
#define B_LO (1024 + 49152)
#define ENERGY_SMEM (1024 + 1024 + 65536)

__global__ __launch_bounds__(128) void energy_hmma_kernel(
    const float* __restrict__ Hp, const float* __restrict__ Hd,
    const float* __restrict__ Wa, float* __restrict__ energy)
{
    extern __shared__ char dsmem[];
    const uint32_t raw  = smem_to_u32(dsmem);
    const uint32_t base = (raw + 1023) & ~1023u;
    char* basep = dsmem + (base - raw);

    float* esum = (float*)(basep);          // [0,512): per-row energy
    float* wa_s = (float*)(basep + 512);    // [512,1024): W_a copy

    const int tid  = threadIdx.x;
    const int lane = tid & 31;
    const int wid  = tid >> 5;
    const int wy   = wid >> 1;              // row half
    const int wx   = wid & 1;               // col half
    const int row0 = blockIdx.x * 128;

    wa_s[tid & 127] = Wa[tid & 127];

    // ldmatrix lane address components (byte offsets within a tile)
    const int q  = lane >> 3;
    const int l7 = lane & 7;
    const uint32_t offA0 = (uint32_t)((wy * 64 + l7 + (q & 1) * 8) * 128 + (q >> 1) * 16);
    const uint32_t offB0 = (uint32_t)((wx * 64 + l7 + (q >> 1) * 8) * 128 + (q & 1) * 16);
    const uint32_t baseAH = base + A_HI, baseAL = base + A_LO;
    const uint32_t baseBH = base + B_HI, baseBL = base + B_LO;

    // X staging map: 16 threads per row (fully coalesced 256B rows)
    const int srow = tid >> 4;              // 0..7
    const int scol = (tid & 15) * 4;        // 0..60

    float acc[4][8][4];
    #pragma unroll
    for (int mt = 0; mt < 4; ++mt)
        #pragma unroll
        for (int nt = 0; nt < 8; ++nt)
            #pragma unroll
            for (int j = 0; j < 4; ++j) acc[mt][nt][j] = 0.f;

    #pragma unroll 1
    for (int ch = 0; ch < 4; ++ch) {
        __syncthreads();   // prior compute done before overwriting tiles

        // --- stage W tiles (pre-swizzled images; L2-hot) ---
        const uint4* wsrc = (const uint4*)(g_Wimg + (size_t)ch * 32768);
        uint4* bh = (uint4*)(basep + B_HI);
        uint4* bl = (uint4*)(basep + B_LO);
        #pragma unroll
        for (int i = 0; i < 8; ++i) {
            bh[tid + i * 128] = wsrc[tid + i * 128];
            bl[tid + i * 128] = wsrc[1024 + tid + i * 128];
        }

        // --- stage X tile: fp32 -> bf16 hi/lo, SW128 swizzled [row][k] ---
        const float* xsrc = ((ch < 2) ? Hp : Hd) + (ch & 1) * 64;
        #pragma unroll
        for (int it = 0; it < 16; ++it) {
            const int r = it * 8 + srow;
            const float4 v = *(const float4*)(xsrc + ((size_t)(row0 + r) << 7) + scol);
            const uint32_t sw = SW128((uint32_t)(r * 128 + scol * 2));
            uint2 hi2, lo2;
            hi2.x = pack_hi2(v.x, v.y);  hi2.y = pack_hi2(v.z, v.w);
            lo2.x = pack_lo2(v.x, v.y);  lo2.y = pack_lo2(v.z, v.w);
            *(uint2*)(basep + A_HI + sw) = hi2;
            *(uint2*)(basep + A_LO + sw) = lo2;
        }
        __syncthreads();

        // --- compute: 4 k-steps of 16; 3 split products ---
        #pragma unroll 1
        for (int ks = 0; ks < 4; ++ks) {
            const uint32_t ks32 = ks * 32;
            uint32_t bhr[4][4], blr[4][4], a[4][4];
            #pragma unroll
            for (int p = 0; p < 4; ++p)
                ldsm4(bhr[p], baseBH + SW128(offB0 + p * 2048 + ks32));
            #pragma unroll
            for (int p = 0; p < 4; ++p)
                ldsm4(blr[p], baseBL + SW128(offB0 + p * 2048 + ks32));
            #pragma unroll
            for (int mt = 0; mt < 4; ++mt)
                ldsm4(a[mt], baseAH + SW128(offA0 + mt * 2048 + ks32));
            #pragma unroll
            for (int mt = 0; mt < 4; ++mt)
                #pragma unroll
                for (int nt = 0; nt < 8; ++nt)
                    mma_bf16(acc[mt][nt], a[mt],
                             bhr[nt >> 1][(nt & 1) * 2], bhr[nt >> 1][(nt & 1) * 2 + 1]);
            #pragma unroll
            for (int mt = 0; mt < 4; ++mt)
                #pragma unroll
                for (int nt = 0; nt < 8; ++nt)
                    mma_bf16(acc[mt][nt], a[mt],
                             blr[nt >> 1][(nt & 1) * 2], blr[nt >> 1][(nt & 1) * 2 + 1]);
            #pragma unroll
            for (int mt = 0; mt < 4; ++mt)
                ldsm4(a[mt], baseAL + SW128(offA0 + mt * 2048 + ks32));
            #pragma unroll
            for (int mt = 0; mt < 4; ++mt)
                #pragma unroll
                for (int nt = 0; nt < 8; ++nt)
                    mma_bf16(acc[mt][nt], a[mt],
                             bhr[nt >> 1][(nt & 1) * 2], bhr[nt >> 1][(nt & 1) * 2 + 1]);
        }
    }

    // --- epilogue ---
    float wa_r[16];
    #pragma unroll
    for (int nt = 0; nt < 8; ++nt) {
        wa_r[nt * 2 + 0] = wa_s[wx * 64 + nt * 8 + (lane & 3) * 2 + 0];
        wa_r[nt * 2 + 1] = wa_s[wx * 64 + nt * 8 + (lane & 3) * 2 + 1];
    }
    __syncthreads();
    esum[tid & 127] = 0.f;
    __syncthreads();

    #pragma unroll
    for (int mt = 0; mt < 4; ++mt) {
        #pragma unroll
        for (int half = 0; half < 2; ++half) {
            float p = 0.f;
            #pragma unroll
            for (int nt = 0; nt < 8; ++nt) {
                p += wa_r[nt * 2 + 0] * tanh_fast(acc[mt][nt][half * 2 + 0]);
                p += wa_r[nt * 2 + 1] * tanh_fast(acc[mt][nt][half * 2 + 1]);
            }
            p += __shfl_xor_sync(0xffffffffu, p, 1);
            p += __shfl_xor_sync(0xffffffffu, p, 2);
            if ((lane & 3) == 0)
                atomicAdd(&esum[wy * 64 + mt * 16 + half * 8 + (lane >> 2)], p);
        }
    }
    __syncthreads();
    energy[row0 + tid] = esum[tid];
}

// ---------------------------------------------------------------------------
// Kernel 2: per-batch scaled softmax over T=2048 (energy in-place -> alpha).
// ---------------------------------------------------------------------------
__global__ __launch_bounds__(256) void softmax_kernel(
    const float* __restrict__ acc_w, const float* __restrict__ ba_p,
    const float* __restrict__ beta_p, float* __restrict__ alpha)
{
    const int b = blockIdx.x;
    const int tid = threadIdx.x;
    __shared__ float sbuf[T_DIM];
    __shared__ float red[256];

    const float* aw = acc_w + (size_t)b * T_DIM;
    float* al = alpha + (size_t)b * T_DIM;

    float wmax = -3.4e38f;
    for (int t = tid; t < T_DIM; t += 256) wmax = fmaxf(wmax, aw[t]);
    red[tid] = wmax;
    __syncthreads();
    for (int s = 128; s > 0; s >>= 1) {
        if (tid < s) red[tid] = fmaxf(red[tid], red[tid + s]);
        __syncthreads();
    }
    const float denom = fmaxf(red[0], 1e-6f);
    __syncthreads();

    const float beta = *beta_p;
    const float bpos = fmaxf(beta, 0.f) + log1pf(expf(-fabsf(beta)));
    const float ba = *ba_p;

    float smax = -3.4e38f;
    for (int t = tid; t < T_DIM; t += 256) {
        const float s = (al[t] + ba) * (1.f + bpos * (aw[t] / denom));
        sbuf[t] = s;
        smax = fmaxf(smax, s);
    }
    red[tid] = smax;
    __syncthreads();
    for (int s = 128; s > 0; s >>= 1) {
        if (tid < s) red[tid] = fmaxf(red[tid], red[tid + s]);
        __syncthreads();
    }
    smax = red[0];
    __syncthreads();

    float ssum = 0.f;
    for (int t = tid; t < T_DIM; t += 256) {
        const float p = expf(sbuf[t] - smax);
        sbuf[t] = p;
        ssum += p;
    }
    red[tid] = ssum;
    __syncthreads();
    for (int s = 128; s > 0; s >>= 1) {
        if (tid < s) red[tid] += red[tid + s];
        __syncthreads();
    }
    const float inv = 1.f / red[0];
    for (int t = tid; t < T_DIM; t += 256) al[t] = sbuf[t] * inv;
}

// ---------------------------------------------------------------------------
// Kernel 3: context[b,h] = sum_t alpha[b,t] * H_pos[b,t,h]
// ---------------------------------------------------------------------------
__global__ __launch_bounds__(512) void context_kernel(
    const float* __restrict__ Hp, const float* __restrict__ alpha,
    float* __restrict__ ctx)
{
    const int b = blockIdx.x;
    const int tid = threadIdx.x;
    const int h = tid & 127;
    const int part = tid >> 7;  // 0..3

    const float* al = alpha + (size_t)b * T_DIM;
    const float* hp = Hp + ((size_t)b * T_DIM) * H_DIM + h;

    float acc = 0.f;
    const int t0 = part * (T_DIM / 4);
    #pragma unroll 8
    for (int t = 0; t < T_DIM / 4; ++t)
        acc += al[t0 + t] * hp[(size_t)(t0 + t) * H_DIM];

    __shared__ float cbuf[512];
    cbuf[tid] = acc;
    __syncthreads();
    if (part == 0)
        ctx[b * H_DIM + h] = cbuf[h] + cbuf[h + 128] + cbuf[h + 256] + cbuf[h + 384];
}

// ---------------------------------------------------------------------------
// Launch. Inputs per metadata order:
//   0 H_pos [B,T,H] f32, 1 H_dyn [B,T,H] f32, 2 acc_w [B,T] f32,
//   3 W_h [H,H] f32, 4 W_d [H,H] f32, 5 W_a [H] f32, 6 b_a [] f32, 7 beta [] f32
// Output: context [B,H] then alpha [B,T]. Energy staged in the alpha region.
// ---------------------------------------------------------------------------
extern "C" void kernel_launch(void* const* d_in, const int* in_sizes, int n_in,
                              void* d_out, int out_size)
{
    const float* Hp   = (const float*)d_in[0];
    const float* Hd   = (const float*)d_in[1];
    const float* accw = (const float*)d_in[2];
    const float* Wh   = (const float*)d_in[3];
    const float* Wd   = (const float*)d_in[4];
    const float* Wa   = (const float*)d_in[5];
    const float* ba   = (const float*)d_in[6];
    const float* beta = (const float*)d_in[7];

    float* out   = (float*)d_out;
    float* ctx   = out;                    // [B, H]
    float* alpha = out + B_DIM * H_DIM;    // [B, T]

    cudaFuncSetAttribute(energy_hmma_kernel,
                         cudaFuncAttributeMaxDynamicSharedMemorySize, ENERGY_SMEM);

    wconv_kernel<<<128, 256>>>(Wh, Wd);
    energy_hmma_kernel<<<BT / 128, 128, ENERGY_SMEM>>>(Hp, Hd, Wa, alpha);
    softmax_kernel<<<B_DIM, 256>>>(accw, ba, beta, alpha);
    context_kernel<<<B_DIM, 512>>>(Hp, alpha, ctx);
}